// round 1
// baseline (speedup 1.0000x reference)
#include <cuda_runtime.h>
#include <cuda_bf16.h>
#include <cstdint>

// ---------------- problem constants ----------------
#define NB    128     // batch
#define CIN   1024
#define HH    14
#define WW    14
#define OO    196     // H*W
#define CF    128     // conv filters
#define TH    128     // code dim
#define QD    258     // CF+2+TH
#define CED   130     // CF+2
#define PD    388     // 2*(CF+2)+TH
#define HP    256
#define GT    256
#define FP    256
#define ASZ   32

// ---------------- scratch (static device globals; no allocation) ----------------
__device__ float g_w2[CIN * 9 * CF];          // transposed conv weights [cin*9][ch]  (~4.7MB)
__device__ float g_xt[NB * OO * CF];          // conv output, [n][o][c]               (~12.9MB)
__device__ float g_att[NB * OO];              // attention logits
__device__ float g_sel[NB * CED];             // selected soft object
__device__ float g_rel[NB * GT];              // relations

__device__ __forceinline__ float xcoord(int o) { return -1.0f + 2.0f * (float)(o / WW) / 13.0f; }
__device__ __forceinline__ float ycoord(int o) { return -1.0f + 2.0f * (float)(o % WW) / 13.0f; }

// ---------------- kernel 1: weight transpose ----------------
__global__ void k_transpose_w(const float* __restrict__ conv_w) {
    int idx = blockIdx.x * 256 + threadIdx.x;       // over CF*CIN*9
    if (idx < CF * CIN * 9) {
        int ch = idx / (CIN * 9);
        int r  = idx - ch * (CIN * 9);              // cin*9 + k
        g_w2[r * CF + ch] = conv_w[idx];
    }
}

// ---------------- kernel 2: 3x3 conv, implicit GEMM ----------------
// grid (7, NB), block 256. Block computes output rows {2*rb, 2*rb+1}, all 128 channels.
// Thread: ch = tid&127, g = tid>>7 (which of the two rows); 14 column accumulators.
#define CCH 8
__global__ void __launch_bounds__(256) k_conv(const float* __restrict__ image,
                                              const float* __restrict__ conv_b) {
    int rb = blockIdx.x, n = blockIdx.y;
    int tid = threadIdx.x;
    int ch = tid & 127, g = tid >> 7;
    int orow = 2 * rb + g;

    __shared__ float img_s[CCH][4][16];   // [cin][tile row][col+1], rows 2rb-1..2rb+2

    float acc[14];
#pragma unroll
    for (int i = 0; i < 14; i++) acc[i] = 0.0f;

    const float* imgn = image + (size_t)n * CIN * OO;

    for (int c0 = 0; c0 < CIN; c0 += CCH) {
        // cooperative load: CCH*4*16 = 512 elements, 2 per thread
#pragma unroll
        for (int e = tid; e < CCH * 4 * 16; e += 256) {
            int cc  = e >> 6;
            int rr  = (e >> 4) & 3;
            int col = e & 15;
            int grow = 2 * rb - 1 + rr;
            int gcol = col - 1;
            float v = 0.0f;
            if (grow >= 0 && grow < HH && gcol >= 0 && gcol < WW)
                v = imgn[(size_t)(c0 + cc) * OO + grow * WW + gcol];
            img_s[cc][rr][col] = v;
        }
        __syncthreads();

#pragma unroll
        for (int cc = 0; cc < CCH; cc++) {
#pragma unroll
            for (int ky = 0; ky < 3; ky++) {
                const float* row = img_s[cc][g + ky];
                float r[16];
#pragma unroll
                for (int i = 0; i < 16; i++) r[i] = row[i];
#pragma unroll
                for (int kx = 0; kx < 3; kx++) {
                    float wv = g_w2[((c0 + cc) * 9 + ky * 3 + kx) * CF + ch];
#pragma unroll
                    for (int col = 0; col < 14; col++)
                        acc[col] = fmaf(wv, r[col + kx], acc[col]);
                }
            }
        }
        __syncthreads();
    }

    float b = conv_b[ch];
#pragma unroll
    for (int col = 0; col < 14; col++) {
        int o = orow * WW + col;
        g_xt[((size_t)n * OO + o) * CF + ch] = acc[col] + b;
    }
}

// ---------------- kernel 3: h_psi attention logits ----------------
// grid (2, NB): block handles 98 positions of one n. 256 threads = HP dims.
__global__ void __launch_bounds__(256) k_hpsi(const float* __restrict__ code,
                                              const float* __restrict__ hp_w0,
                                              const float* __restrict__ hp_b0,
                                              const float* __restrict__ hp_w1,
                                              const float* __restrict__ hp_b1) {
    int s = blockIdx.x, n = blockIdx.y;
    int tid = threadIdx.x;
    __shared__ float qe_s[QD];
    __shared__ float red_s[8];

    if (tid < TH) qe_s[CED + tid] = code[n * TH + tid];   // code part, constant over o
    float w1v = hp_w1[tid];
    float b0v = hp_b0[tid];
    float b1v = hp_b1[0];
    const float* xtn = g_xt + (size_t)n * OO * CF;

    int o0 = s * 98, o1 = o0 + 98;
    for (int o = o0; o < o1; o++) {
        __syncthreads();
        if (tid < CF) qe_s[tid] = xtn[o * CF + tid];
        if (tid == CF)     qe_s[CF]     = xcoord(o);
        if (tid == CF + 1) qe_s[CF + 1] = ycoord(o);
        __syncthreads();

        float sum = b0v;
#pragma unroll 4
        for (int d = 0; d < QD; d++)
            sum = fmaf(qe_s[d], hp_w0[d * HP + tid], sum);
        float a = fmaxf(sum, 0.0f);
        float p = a * w1v;
        // block reduce p
#pragma unroll
        for (int off = 16; off > 0; off >>= 1) p += __shfl_xor_sync(0xffffffffu, p, off);
        if ((tid & 31) == 0) red_s[tid >> 5] = p;
        __syncthreads();
        if (tid == 0) {
            float q = 0.0f;
#pragma unroll
            for (int i = 0; i < 8; i++) q += red_s[i];
            g_att[n * OO + o] = q + b1v;
        }
    }
}

// ---------------- kernel 4: softmax over objects + soft selection ----------------
// grid NB, 256 threads.
__global__ void __launch_bounds__(256) k_softsel() {
    int n = blockIdx.x;
    int tid = threadIdx.x;
    __shared__ float att_s[OO];
    __shared__ float red_s[8];

    if (tid < OO) att_s[tid] = g_att[n * OO + tid];
    __syncthreads();

    // max
    float v = (tid < OO) ? att_s[tid] : -1e30f;
#pragma unroll
    for (int off = 16; off > 0; off >>= 1) v = fmaxf(v, __shfl_xor_sync(0xffffffffu, v, off));
    if ((tid & 31) == 0) red_s[tid >> 5] = v;
    __syncthreads();
    float m = -1e30f;
#pragma unroll
    for (int i = 0; i < 8; i++) m = fmaxf(m, red_s[i]);
    __syncthreads();

    // exp + sum
    float e = (tid < OO) ? expf(att_s[tid] - m) : 0.0f;
    float sv = e;
#pragma unroll
    for (int off = 16; off > 0; off >>= 1) sv += __shfl_xor_sync(0xffffffffu, sv, off);
    if ((tid & 31) == 0) red_s[tid >> 5] = sv;
    __syncthreads();
    float tot = 0.0f;
#pragma unroll
    for (int i = 0; i < 8; i++) tot += red_s[i];
    if (tid < OO) att_s[tid] = e / tot;
    __syncthreads();

    // selected[d] = sum_o sel[o] * ce[o][d]
    if (tid < CED) {
        const float* xtn = g_xt + (size_t)n * OO * CF;
        float acc = 0.0f;
        for (int o = 0; o < OO; o++) {
            float c;
            if (tid < CF)            c = xtn[o * CF + tid];
            else if (tid == CF)      c = xcoord(o);
            else                     c = ycoord(o);
            acc = fmaf(att_s[o], c, acc);
        }
        g_sel[n * CED + tid] = acc;
    }
}

// ---------------- kernel 5: g_theta MLP + object sum ----------------
// grid NB, 256 threads = GT output units; TILE_O=4 positions per pass.
#define TO 4
__global__ void __launch_bounds__(256) k_gtheta(const float* __restrict__ code,
                                                const float* __restrict__ gt_w0,
                                                const float* __restrict__ gt_b0,
                                                const float* __restrict__ gt_w1,
                                                const float* __restrict__ gt_b1) {
    int n = blockIdx.x;
    int tid = threadIdx.x;
    __shared__ float pairs_s[TO][PD];
    __shared__ float g1_s[TO][GT];
    __shared__ float sel_s[CED];
    __shared__ float code_s[TH];

    if (tid < CED) sel_s[tid] = g_sel[n * CED + tid];
    if (tid < TH)  code_s[tid] = code[n * TH + tid];

    const float* xtn = g_xt + (size_t)n * OO * CF;
    float b0 = gt_b0[tid], b1 = gt_b1[tid];
    float relacc = 0.0f;

    for (int ob = 0; ob < OO; ob += TO) {
        __syncthreads();
        for (int e = tid; e < TO * PD; e += 256) {
            int t = e / PD;
            int p = e - t * PD;
            int o = ob + t;
            float v;
            if (p < CF)            v = xtn[o * CF + p];
            else if (p == CF)      v = xcoord(o);
            else if (p == CF + 1)  v = ycoord(o);
            else if (p < QD)       v = code_s[p - CED];
            else                   v = sel_s[p - QD];
            pairs_s[t][p] = v;
        }
        __syncthreads();

        float g1[TO];
#pragma unroll
        for (int t = 0; t < TO; t++) g1[t] = b0;
#pragma unroll 4
        for (int p = 0; p < PD; p++) {
            float w = gt_w0[p * GT + tid];
#pragma unroll
            for (int t = 0; t < TO; t++) g1[t] = fmaf(pairs_s[t][p], w, g1[t]);
        }
#pragma unroll
        for (int t = 0; t < TO; t++) g1_s[t][tid] = fmaxf(g1[t], 0.0f);
        __syncthreads();

        float g2[TO];
#pragma unroll
        for (int t = 0; t < TO; t++) g2[t] = b1;
#pragma unroll 4
        for (int h = 0; h < GT; h++) {
            float w = gt_w1[h * GT + tid];
#pragma unroll
            for (int t = 0; t < TO; t++) g2[t] = fmaf(g1_s[t][h], w, g2[t]);
        }
#pragma unroll
        for (int t = 0; t < TO; t++) relacc += fmaxf(g2[t], 0.0f);
    }
    g_rel[n * GT + tid] = relacc;
}

// ---------------- kernel 6: f_phi head ----------------
// grid NB, 256 threads.
__global__ void __launch_bounds__(256) k_fphi(const float* __restrict__ fp_w0,
                                              const float* __restrict__ fp_b0,
                                              const float* __restrict__ fp_w1,
                                              const float* __restrict__ fp_b1,
                                              float* __restrict__ out) {
    int n = blockIdx.x;
    int tid = threadIdx.x;
    __shared__ float f_s[FP];

    const float* rel = g_rel + n * GT;
    float s = fp_b0[tid];
#pragma unroll 4
    for (int h = 0; h < GT; h++)
        s = fmaf(rel[h], fp_w0[h * FP + tid], s);
    f_s[tid] = fmaxf(s, 0.0f);
    __syncthreads();

    if (tid < ASZ) {
        float s2 = fp_b1[tid];
#pragma unroll 4
        for (int h = 0; h < FP; h++)
            s2 = fmaf(f_s[h], fp_w1[h * ASZ + tid], s2);
        out[n * ASZ + tid] = s2;
    }
}

// ---------------- launch ----------------
extern "C" void kernel_launch(void* const* d_in, const int* in_sizes, int n_in,
                              void* d_out, int out_size) {
    const float* image  = (const float*)d_in[0];
    const float* code   = (const float*)d_in[1];
    const float* conv_w = (const float*)d_in[2];
    const float* conv_b = (const float*)d_in[3];
    const float* hp_w0  = (const float*)d_in[4];
    const float* hp_b0  = (const float*)d_in[5];
    const float* hp_w1  = (const float*)d_in[6];
    const float* hp_b1  = (const float*)d_in[7];
    const float* gt_w0  = (const float*)d_in[8];
    const float* gt_b0  = (const float*)d_in[9];
    const float* gt_w1  = (const float*)d_in[10];
    const float* gt_b1  = (const float*)d_in[11];
    const float* fp_w0  = (const float*)d_in[12];
    const float* fp_b0  = (const float*)d_in[13];
    const float* fp_w1  = (const float*)d_in[14];
    const float* fp_b1  = (const float*)d_in[15];
    float* out = (float*)d_out;

    k_transpose_w<<<(CF * CIN * 9 + 255) / 256, 256>>>(conv_w);
    k_conv<<<dim3(7, NB), 256>>>(image, conv_b);
    k_hpsi<<<dim3(2, NB), 256>>>(code, hp_w0, hp_b0, hp_w1, hp_b1);
    k_softsel<<<NB, 256>>>();
    k_gtheta<<<NB, 256>>>(code, gt_w0, gt_b0, gt_w1, gt_b1);
    k_fphi<<<NB, 256>>>(fp_w0, fp_b0, fp_w1, fp_b1, out);
}